// round 2
// baseline (speedup 1.0000x reference)
#include <cuda_runtime.h>
#include <cuda_bf16.h>

typedef unsigned long long ull;

// Problem constants
#define N_ROWS   65536      // 64 * 1024 tokens
#define K_CODES  1024
#define D_DIM    64
#define BLOCK_ROWS 128
#define TILE_C   64
#define THREADS  256
#define NUM_BLOCKS (N_ROWS / BLOCK_ROWS)   // 512

// Output layout (floats): [quantized 4194304][loss 1][indices 65536]
#define OUT_Q    0
#define OUT_LOSS (N_ROWS * D_DIM)
#define OUT_IDX  (OUT_LOSS + 1)

__device__ float g_normE[K_CODES];
__device__ float g_partials[NUM_BLOCKS];

// ---- packed f32x2 helpers -------------------------------------------------
__device__ __forceinline__ ull f32x2_fma(ull a, ull b, ull c) {
    ull d;
    asm("fma.rn.f32x2 %0, %1, %2, %3;" : "=l"(d) : "l"(a), "l"(b), "l"(c));
    return d;
}
__device__ __forceinline__ ull f32x2_dup(float x) {
    ull d;
    asm("mov.b64 %0, {%1, %1};" : "=l"(d) : "f"(x));
    return d;
}
__device__ __forceinline__ float2 f32x2_unpack(ull v) {
    float2 r;
    asm("mov.b64 {%0, %1}, %2;" : "=f"(r.x), "=f"(r.y) : "l"(v));
    return r;
}

// ---------------------------------------------------------------------------
// Kernel 1: codebook squared norms  ||e_k||^2
// ---------------------------------------------------------------------------
__global__ void vq_norm_kernel(const float* __restrict__ E) {
    int k = blockIdx.x * blockDim.x + threadIdx.x;
    if (k < K_CODES) {
        const float4* e = (const float4*)(E + k * D_DIM);
        float s = 0.f;
#pragma unroll
        for (int i = 0; i < D_DIM / 4; ++i) {
            float4 v = e[i];
            s += v.x * v.x + v.y * v.y + v.z * v.z + v.w * v.w;
        }
        g_normE[k] = s;
    }
}

// ---------------------------------------------------------------------------
// Kernel 2: fused distance-GEMM (FFMA2) + argmin + gather + partial loss
//   block: 128 rows x 1024 codes, code tiles of 64, D=64 resident in smem
//   accumulators packed f32x2 across row pairs; B tile stored duplicated so
//   the broadcast operand is a single conflict-free LDS.64
// ---------------------------------------------------------------------------
__global__ __launch_bounds__(THREADS) void vq_main_kernel(
    const float* __restrict__ X,   // [N, D]
    const float* __restrict__ E,   // [K, D]
    float* __restrict__ out)
{
    extern __shared__ float smem[];
    float* As   = smem;                            // [64][128]  (D-major)
    float* Bs2  = As + D_DIM * BLOCK_ROWS;         // [64][128]  dup pairs {b,b}
    float* redV = Bs2 + D_DIM * TILE_C * 2;        // [128][16]
    int*   redI = (int*)(redV + BLOCK_ROWS * 16);  // [128][16]
    float* sLoss = (float*)(redI + BLOCK_ROWS * 16); // [128]

    const int t = threadIdx.x;
    const int rowBase = blockIdx.x * BLOCK_ROWS;

    // ---- load A tile (128 rows x 64 D), transposed into As[d][r] ----
#pragma unroll
    for (int it = 0; it < 8; ++it) {
        int idx = t + it * THREADS;      // 0..2047
        int r  = idx & 127;
        int d4 = idx >> 7;               // 0..15
        float4 v = *(const float4*)(X + (size_t)(rowBase + r) * D_DIM + d4 * 4);
        As[(d4 * 4 + 0) * BLOCK_ROWS + r] = v.x;
        As[(d4 * 4 + 1) * BLOCK_ROWS + r] = v.y;
        As[(d4 * 4 + 2) * BLOCK_ROWS + r] = v.z;
        As[(d4 * 4 + 3) * BLOCK_ROWS + r] = v.w;
    }

    const int tr = t >> 4;   // 0..15 -> rows tr*8 .. tr*8+7 (4 f32x2 pairs)
    const int tc = t & 15;   // 0..15 -> cols {tc, tc+16, tc+32, tc+48}

    float minv[8];
    int   mini[8];
#pragma unroll
    for (int i = 0; i < 8; ++i) { minv[i] = 3.4e38f; mini[i] = 0; }

    const ull neg2 = f32x2_dup(-2.0f);

#pragma unroll 1
    for (int tile = 0; tile < K_CODES / TILE_C; ++tile) {
        __syncthreads();   // As ready (tile 0) / Bs2 consumed (tile > 0)
        // ---- load B tile (64 codes x 64 D) duplicated: Bs2[d][2c]=[2c+1]=E ----
#pragma unroll
        for (int it = 0; it < 4; ++it) {
            int idx = t + it * THREADS;  // 0..1023
            int c  = idx & 63;
            int d4 = idx >> 6;           // 0..15
            float4 v = *(const float4*)(E + (size_t)(tile * TILE_C + c) * D_DIM + d4 * 4);
            *(float2*)&Bs2[(d4 * 4 + 0) * 128 + c * 2] = make_float2(v.x, v.x);
            *(float2*)&Bs2[(d4 * 4 + 1) * 128 + c * 2] = make_float2(v.y, v.y);
            *(float2*)&Bs2[(d4 * 4 + 2) * 128 + c * 2] = make_float2(v.z, v.z);
            *(float2*)&Bs2[(d4 * 4 + 3) * 128 + c * 2] = make_float2(v.w, v.w);
        }
        __syncthreads();

        ull acc[4][4];
#pragma unroll
        for (int i = 0; i < 4; ++i)
#pragma unroll
            for (int j = 0; j < 4; ++j) acc[i][j] = 0ull;

#pragma unroll 16
        for (int d = 0; d < D_DIM; ++d) {
            // a: 4 packed row-pairs (rows tr*8 .. tr*8+7), two 16B loads
            const ull* arow = (const ull*)&As[d * BLOCK_ROWS + tr * 8];
            ulonglong2 a01 = *(const ulonglong2*)(arow);
            ulonglong2 a23 = *(const ulonglong2*)(arow + 2);
            ull ap[4] = {a01.x, a01.y, a23.x, a23.y};
            // b: 4 duplicated pairs {b,b}, strided cols -> conflict-free LDS.64
            ull bp[4];
#pragma unroll
            for (int j = 0; j < 4; ++j)
                bp[j] = *(const ull*)&Bs2[d * 128 + (tc + 16 * j) * 2];
#pragma unroll
            for (int i = 0; i < 4; ++i)
#pragma unroll
                for (int j = 0; j < 4; ++j)
                    acc[i][j] = f32x2_fma(ap[i], bp[j], acc[i][j]);
        }

        // ---- tile epilogue: dist = ||e||^2 - 2*dot ; update running argmin ----
#pragma unroll
        for (int j = 0; j < 4; ++j) {
            int code = tile * TILE_C + j * 16 + tc;
            ull ne2 = f32x2_dup(g_normE[code]);
#pragma unroll
            for (int i = 0; i < 4; ++i) {
                float2 dist = f32x2_unpack(f32x2_fma(acc[i][j], neg2, ne2));
                if (dist.x < minv[2 * i])     { minv[2 * i]     = dist.x; mini[2 * i]     = code; }
                if (dist.y < minv[2 * i + 1]) { minv[2 * i + 1] = dist.y; mini[2 * i + 1] = code; }
            }
        }
    }

    // ---- cross-thread argmin reduction (16 column-threads per row) ----
    __syncthreads();
#pragma unroll
    for (int i = 0; i < 8; ++i) {
        int r = tr * 8 + i;
        redV[r * 16 + tc] = minv[i];
        redI[r * 16 + tc] = mini[i];
    }
    __syncthreads();

    if (t < BLOCK_ROWS) {
        int r = t;
        float bv = redV[r * 16];
        int   bi = redI[r * 16];
#pragma unroll
        for (int j = 1; j < 16; ++j) {
            float v = redV[r * 16 + j];
            int   c = redI[r * 16 + j];
            if (v < bv || (v == bv && c < bi)) { bv = v; bi = c; }
        }

        // gather codebook row, write quantized + index, accumulate loss
        const float4* erow = (const float4*)(E + (size_t)bi * D_DIM);
        float* qout = out + OUT_Q + (size_t)(rowBase + r) * D_DIM;
        float lsum = 0.f;
#pragma unroll
        for (int d4 = 0; d4 < D_DIM / 4; ++d4) {
            float4 q = erow[d4];
            float x0 = As[(d4 * 4 + 0) * BLOCK_ROWS + r];
            float x1 = As[(d4 * 4 + 1) * BLOCK_ROWS + r];
            float x2 = As[(d4 * 4 + 2) * BLOCK_ROWS + r];
            float x3 = As[(d4 * 4 + 3) * BLOCK_ROWS + r];
            float e0 = q.x - x0, e1 = q.y - x1, e2 = q.z - x2, e3 = q.w - x3;
            lsum += e0 * e0 + e1 * e1 + e2 * e2 + e3 * e3;
            *(float4*)(qout + d4 * 4) = q;
        }
        out[OUT_IDX + rowBase + r] = (float)bi;
        sLoss[r] = lsum;
    }
    __syncthreads();

    // deterministic in-block loss reduction (fixed tree)
    if (t < 64) sLoss[t] += sLoss[t + 64];
    __syncthreads();
    if (t < 32) sLoss[t] += sLoss[t + 32];
    __syncthreads();
    if (t == 0) {
        float s = 0.f;
#pragma unroll
        for (int i = 0; i < 32; ++i) s += sLoss[i];
        g_partials[blockIdx.x] = s;
    }
}

// ---------------------------------------------------------------------------
// Kernel 3: deterministic final loss reduction
//   loss = q_loss + 0.25*e_loss = 1.25 * mean((q - x)^2)
// ---------------------------------------------------------------------------
__global__ void vq_loss_kernel(float* __restrict__ out) {
    __shared__ float sh[NUM_BLOCKS];
    int t = threadIdx.x;
    sh[t] = g_partials[t];
    __syncthreads();
    for (int s = NUM_BLOCKS / 2; s > 0; s >>= 1) {
        if (t < s) sh[t] += sh[t + s];
        __syncthreads();
    }
    if (t == 0)
        out[OUT_LOSS] = sh[0] * (1.25f / (float)(N_ROWS * D_DIM));
}

// ---------------------------------------------------------------------------
extern "C" void kernel_launch(void* const* d_in, const int* in_sizes, int n_in,
                              void* d_out, int out_size) {
    const float* X = (const float*)d_in[0];   // [64,1024,64] fp32
    const float* E = (const float*)d_in[1];   // [1024,64]   fp32
    float* out = (float*)d_out;

    const int SMEM_BYTES =
        (D_DIM * BLOCK_ROWS + D_DIM * TILE_C * 2 + BLOCK_ROWS * 16) * 4 // As,Bs2,redV
        + BLOCK_ROWS * 16 * 4                                            // redI
        + BLOCK_ROWS * 4;                                                // sLoss

    cudaFuncSetAttribute(vq_main_kernel,
                         cudaFuncAttributeMaxDynamicSharedMemorySize, SMEM_BYTES);

    vq_norm_kernel<<<(K_CODES + 255) / 256, 256>>>(E);
    vq_main_kernel<<<NUM_BLOCKS, THREADS, SMEM_BYTES>>>(X, E, out);
    vq_loss_kernel<<<1, NUM_BLOCKS>>>(out);
}

// round 4
// speedup vs baseline: 1.3749x; 1.3749x over previous
#include <cuda_runtime.h>
#include <cuda_bf16.h>
#include <cstdint>

// ---------------- problem constants ----------------
#define N_ROWS   65536
#define K_CODES  1024
#define D_DIM    64
#define M_TILE   128                    // rows per CTA
#define THREADS  256
#define NUM_BLOCKS (N_ROWS / M_TILE)    // 512
#define N_MB     (N_ROWS / 16)          // 4096 A row-blocks
#define N_NB     (K_CODES / 8)          // 128 B code-blocks
#define CAP      48
#define MARGIN   0.0625f

// Output layout (floats): [quantized 4194304][loss 1][indices 65536]
#define OUT_LOSS (N_ROWS * D_DIM)
#define OUT_IDX  (OUT_LOSS + 1)

// ---------------- device globals ----------------
// A fragments: [mb][kb][lane][reg] u32 (2 bf16 each), mma m16n8k16 order
__device__ uint32_t g_Ah[N_MB * 4 * 32 * 4];   // 8 MB
__device__ uint32_t g_Am[N_MB * 4 * 32 * 4];   // 8 MB
// B fragments: [nb][kb][lane][reg(2)] u32
__device__ uint32_t g_Bh[N_NB * 4 * 32 * 2];   // 128 KB
__device__ uint32_t g_Bm[N_NB * 4 * 32 * 2];   // 128 KB
__device__ float g_normE[K_CODES];
__device__ float g_partials[NUM_BLOCKS];

// ---------------- smem layout (bytes) ----------------
#define SM_B     0        // 65536: [plane(2)][nbl(32)][kb(4)][lane(32)][reg(2)] u32
#define SM_NORM  65536    // 4096: 1024 floats
#define SM_CANDV 69632    // 24576: 128 * CAP floats
#define SM_CANDI 94208    // 12288: 128 * CAP u16
#define SM_CNT   106496   // 512: 128 ints
#define SM_TOTAL 107008

// ---------------- helpers ----------------
__device__ __forceinline__ uint32_t pack_bf16(float lo, float hi) {
    __nv_bfloat16 a = __float2bfloat16(lo);
    __nv_bfloat16 b = __float2bfloat16(hi);
    uint16_t ua = *(uint16_t*)&a, ub = *(uint16_t*)&b;
    return (uint32_t)ua | ((uint32_t)ub << 16);
}
__device__ __forceinline__ float bf16val(float v) {
    __nv_bfloat16 b = __float2bfloat16(v);
    return __bfloat162float(b);
}
__device__ __forceinline__ void mma_bf16(float* c, const uint32_t* a,
                                         uint32_t b0, uint32_t b1) {
    asm volatile(
        "mma.sync.aligned.m16n8k16.row.col.f32.bf16.bf16.f32 "
        "{%0,%1,%2,%3}, {%4,%5,%6,%7}, {%8,%9}, {%0,%1,%2,%3};"
        : "+f"(c[0]), "+f"(c[1]), "+f"(c[2]), "+f"(c[3])
        : "r"(a[0]), "r"(a[1]), "r"(a[2]), "r"(a[3]), "r"(b0), "r"(b1));
}

// ---------------------------------------------------------------------------
// Prep A: split (-2*X) into (hi, mid) bf16 planes, mma-fragment order
//   tid -> (mb, kb, lane, reg);  a-reg mapping per PTX m16n8k16:
//   row = g + (reg&1)*8, col = tg*2 + (reg&2)*4, g=lane>>2, tg=lane&3
// ---------------------------------------------------------------------------
__global__ void vq_prepA(const float* __restrict__ X) {
    int tid = blockIdx.x * blockDim.x + threadIdx.x;
    if (tid >= N_MB * 4 * 32 * 4) return;
    int reg = tid & 3, lane = (tid >> 2) & 31, kb = (tid >> 7) & 3, mb = tid >> 9;
    int g = lane >> 2, tg = lane & 3;
    int row = mb * 16 + g + ((reg & 1) << 3);
    int col = kb * 16 + tg * 2 + ((reg & 2) << 2);
    const float* xp = X + (size_t)row * D_DIM + col;
    float v0 = -2.0f * xp[0], v1 = -2.0f * xp[1];
    float h0 = bf16val(v0), h1 = bf16val(v1);
    g_Ah[tid] = pack_bf16(v0, v1);          // pack rounds again == h0,h1
    g_Am[tid] = pack_bf16(v0 - h0, v1 - h1);
}

// ---------------------------------------------------------------------------
// Prep B: split E into (hi, mid) bf16 planes, mma-fragment order
//   b-reg mapping: k = tg*2 + reg*8 + {0,1}, n = g
// ---------------------------------------------------------------------------
__global__ void vq_prepB(const float* __restrict__ E) {
    int tid = blockIdx.x * blockDim.x + threadIdx.x;
    if (tid >= N_NB * 4 * 32 * 2) return;
    int reg = tid & 1, lane = (tid >> 1) & 31, kb = (tid >> 6) & 3, nb = tid >> 8;
    int g = lane >> 2, tg = lane & 3;
    int code = nb * 8 + g;
    int k = kb * 16 + tg * 2 + reg * 8;
    const float* ep = E + (size_t)code * D_DIM + k;
    float v0 = ep[0], v1 = ep[1];
    float h0 = bf16val(v0), h1 = bf16val(v1);
    g_Bh[tid] = pack_bf16(v0, v1);
    g_Bm[tid] = pack_bf16(v0 - h0, v1 - h1);
}

// ---------------------------------------------------------------------------
// Codebook norms
// ---------------------------------------------------------------------------
__global__ void vq_norm_kernel(const float* __restrict__ E) {
    int k = blockIdx.x * blockDim.x + threadIdx.x;
    if (k < K_CODES) {
        const float4* e = (const float4*)(E + (size_t)k * D_DIM);
        float s = 0.f;
#pragma unroll
        for (int i = 0; i < D_DIM / 4; ++i) {
            float4 v = e[i];
            s += v.x * v.x + v.y * v.y + v.z * v.z + v.w * v.w;
        }
        g_normE[k] = s;
    }
}

// ---------------------------------------------------------------------------
// Main: HMMA split distance GEMM + margin-candidate argmin + exact refine
// ---------------------------------------------------------------------------
__global__ __launch_bounds__(THREADS) void vq_main_kernel(
    const float* __restrict__ X, const float* __restrict__ E,
    float* __restrict__ out)
{
    extern __shared__ char smem[];
    float* snorm = (float*)(smem + SM_NORM);
    float* candV = (float*)(smem + SM_CANDV);
    unsigned short* candI = (unsigned short*)(smem + SM_CANDI);
    int* cnt = (int*)(smem + SM_CNT);

    const int t = threadIdx.x;
    const int w = t >> 5, l = t & 31;
    const int g = l >> 2, tg = l & 3;
    const int rowBase = blockIdx.x * M_TILE;

    if (t < M_TILE) cnt[t] = 0;
    for (int i = t; i < K_CODES; i += THREADS) snorm[i] = g_normE[i];

    // A fragments in registers for this warp's 16 rows (mb global)
    const int mb = blockIdx.x * 8 + w;
    uint4 aH[4], aM[4];
#pragma unroll
    for (int kb = 0; kb < 4; ++kb) {
        aH[kb] = *(const uint4*)&g_Ah[((mb * 4 + kb) * 32 + l) * 4];
        aM[kb] = *(const uint4*)&g_Am[((mb * 4 + kb) * 32 + l) * 4];
    }

    float minv0 = 3.4e38f, minv1 = 3.4e38f;
    const int rL0 = w * 16 + g, rL1 = rL0 + 8;

#pragma unroll 1
    for (int tile = 0; tile < 4; ++tile) {
        __syncthreads();
        // stage B tile (32 nblocks, both planes) = 64KB
        {
            const uint4* srcH = (const uint4*)(g_Bh + tile * 8192);
            const uint4* srcM = (const uint4*)(g_Bm + tile * 8192);
            uint4* dst = (uint4*)(smem + SM_B);
#pragma unroll
            for (int i = 0; i < 16; ++i) {
                int idx = t + i * THREADS;     // < 4096
                dst[idx] = (idx < 2048) ? srcH[idx] : srcM[idx - 2048];
            }
        }
        __syncthreads();

        const uint2* bptr = (const uint2*)(smem + SM_B) + l;
#pragma unroll 2
        for (int nbl = 0; nbl < 32; ++nbl) {
            float acc[4] = {0.f, 0.f, 0.f, 0.f};
#pragma unroll
            for (int kb = 0; kb < 4; ++kb) {
                uint2 bh = bptr[(nbl * 4 + kb) * 32];
                uint2 bm = bptr[((32 + nbl) * 4 + kb) * 32];
                mma_bf16(acc, (const uint32_t*)&aH[kb], bh.x, bh.y);
                mma_bf16(acc, (const uint32_t*)&aH[kb], bm.x, bm.y);
                mma_bf16(acc, (const uint32_t*)&aM[kb], bh.x, bh.y);
            }
            const int c0 = tile * 256 + nbl * 8 + tg * 2;
            const float n0 = snorm[c0], n1 = snorm[c0 + 1];
            float d;
            // row rL0, codes c0, c0+1  (ascending)
            d = acc[0] + n0;
            if (d < minv0 + MARGIN) {
                int p = atomicAdd(&cnt[rL0], 1);
                if (p < CAP) { candV[rL0 * CAP + p] = d; candI[rL0 * CAP + p] = (unsigned short)c0; }
            }
            if (d < minv0) minv0 = d;
            d = acc[1] + n1;
            if (d < minv0 + MARGIN) {
                int p = atomicAdd(&cnt[rL0], 1);
                if (p < CAP) { candV[rL0 * CAP + p] = d; candI[rL0 * CAP + p] = (unsigned short)(c0 + 1); }
            }
            if (d < minv0) minv0 = d;
            // row rL1
            d = acc[2] + n0;
            if (d < minv1 + MARGIN) {
                int p = atomicAdd(&cnt[rL1], 1);
                if (p < CAP) { candV[rL1 * CAP + p] = d; candI[rL1 * CAP + p] = (unsigned short)c0; }
            }
            if (d < minv1) minv1 = d;
            d = acc[3] + n1;
            if (d < minv1 + MARGIN) {
                int p = atomicAdd(&cnt[rL1], 1);
                if (p < CAP) { candV[rL1 * CAP + p] = d; candI[rL1 * CAP + p] = (unsigned short)(c0 + 1); }
            }
            if (d < minv1) minv1 = d;
        }
    }
    __syncthreads();

    // ---- exact refine + epilogue: one thread per row ----
    float* sLoss = (float*)(smem + SM_B);   // reuse B area
    if (t < M_TILE) {
        const int r = t;
        const float* xr = X + (size_t)(rowBase + r) * D_DIM;
        float bv = 3.4e38f;
        int bi = K_CODES;
        const int count = cnt[r];
        if (count > CAP) {
            // overflow fallback: exact scan over all codes (rare/never)
            for (int c = 0; c < K_CODES; ++c) {
                const float* er = E + (size_t)c * D_DIM;
                float dot = 0.f;
#pragma unroll 16
                for (int dd = 0; dd < D_DIM; ++dd) dot = fmaf(xr[dd], er[dd], dot);
                float dv = fmaf(-2.f, dot, g_normE[c]);
                if (dv < bv) { bv = dv; bi = c; }
            }
        } else {
            float mA = 3.4e38f;
            for (int i = 0; i < count; ++i)
                mA = fminf(mA, candV[r * CAP + i]);
            for (int i = 0; i < count; ++i) {
                if (candV[r * CAP + i] > mA + MARGIN) continue;
                int c = candI[r * CAP + i];
                const float* er = E + (size_t)c * D_DIM;
                float dot = 0.f;
#pragma unroll 16
                for (int dd = 0; dd < D_DIM; ++dd) dot = fmaf(xr[dd], er[dd], dot);
                float dv = fmaf(-2.f, dot, g_normE[c]);
                if (dv < bv || (dv == bv && c < bi)) { bv = dv; bi = c; }
            }
        }
        // gather codebook row, write quantized + index, accumulate loss
        const float4* erow = (const float4*)(E + (size_t)bi * D_DIM);
        const float4* xrow = (const float4*)xr;
        float* qout = out + (size_t)(rowBase + r) * D_DIM;
        float lsum = 0.f;
#pragma unroll
        for (int i = 0; i < D_DIM / 4; ++i) {
            float4 q = erow[i], x = xrow[i];
            float e0 = q.x - x.x, e1 = q.y - x.y, e2 = q.z - x.z, e3 = q.w - x.w;
            lsum += e0 * e0 + e1 * e1 + e2 * e2 + e3 * e3;
            *(float4*)(qout + i * 4) = q;
        }
        out[OUT_IDX + rowBase + r] = (float)bi;
        sLoss[r] = lsum;
    }
    __syncthreads();
    if (t < 64) sLoss[t] += sLoss[t + 64];
    __syncthreads();
    if (t < 32) sLoss[t] += sLoss[t + 32];
    __syncthreads();
    if (t == 0) {
        float s = 0.f;
#pragma unroll
        for (int i = 0; i < 32; ++i) s += sLoss[i];
        g_partials[blockIdx.x] = s;
    }
}

// ---------------------------------------------------------------------------
// Final loss:  loss = 1.25 * mean((q - x)^2), deterministic tree
// ---------------------------------------------------------------------------
__global__ void vq_loss_kernel(float* __restrict__ out) {
    __shared__ float sh[NUM_BLOCKS];
    int t = threadIdx.x;
    sh[t] = g_partials[t];
    __syncthreads();
    for (int s = NUM_BLOCKS / 2; s > 0; s >>= 1) {
        if (t < s) sh[t] += sh[t + s];
        __syncthreads();
    }
    if (t == 0) out[OUT_LOSS] = sh[0] * (1.25f / (float)(N_ROWS * D_DIM));
}

// ---------------------------------------------------------------------------
extern "C" void kernel_launch(void* const* d_in, const int* in_sizes, int n_in,
                              void* d_out, int out_size) {
    const float* X = (const float*)d_in[0];
    const float* E = (const float*)d_in[1];
    float* out = (float*)d_out;

    cudaFuncSetAttribute(vq_main_kernel,
                         cudaFuncAttributeMaxDynamicSharedMemorySize, SM_TOTAL);

    vq_prepA<<<(N_MB * 4 * 32 * 4 + 255) / 256, 256>>>(X);
    vq_prepB<<<(N_NB * 4 * 32 * 2 + 255) / 256, 256>>>(E);
    vq_norm_kernel<<<(K_CODES + 255) / 256, 256>>>(E);
    vq_main_kernel<<<NUM_BLOCKS, THREADS, SM_TOTAL>>>(X, E, out);
    vq_loss_kernel<<<1, NUM_BLOCKS>>>(out);
}